// round 9
// baseline (speedup 1.0000x reference)
#include <cuda_runtime.h>
#include <math.h>
#include <float.h>

#define BB 64
#define QQ 900
#define TT 128
#define C1 14    // NUM_CLASSES+1
#define QP 912   // padded Q stride (multiple of 4) for the transposed prob table

// Scratch (static device globals; no allocation)
__device__ __align__(16) float g_cost[(size_t)BB*TT*QQ];   // cost[b][t][q]
__device__ __align__(16) float g_probT[(size_t)BB*C1*QP];  // -softmax, [b][c][q]
__device__ float g_lse[BB*QQ];
__device__ int   g_pred[BB*TT];              // matched query index per (b,t)
__device__ float g_partial[BB];
__device__ unsigned g_count = 0;

typedef unsigned long long u64;

__device__ __forceinline__ u64 pk2(float lo, float hi) {
    u64 r;
    asm("mov.b64 %0, {%1, %2};" : "=l"(r) : "f"(lo), "f"(hi));
    return r;
}
__device__ __forceinline__ u64 addx2(u64 a, u64 b) {
    u64 r;
    asm("add.rn.f32x2 %0, %1, %2;" : "=l"(r) : "l"(a), "l"(b));
    return r;
}
__device__ __forceinline__ void up2(u64 v, float& lo, float& hi) {
    asm("mov.b64 {%0, %1}, %2;" : "=f"(lo), "=f"(hi) : "l"(v));
}

// ---------------------------------------------------------------------------
// Kernel 0: softmax -> transposed negative-prob table + logsumexp
// grid (4, B) x 256
// ---------------------------------------------------------------------------
__global__ void __launch_bounds__(256) softmax_kernel(const float* __restrict__ pc)
{
    int b = blockIdx.y;
    int q = blockIdx.x * 256 + threadIdx.x;
    if (q >= QQ) return;

    const float* lg = pc + ((size_t)b * QQ + q) * C1;
    float l[C1];
    float m = -FLT_MAX;
    #pragma unroll
    for (int c = 0; c < C1; c++) { l[c] = lg[c]; m = fmaxf(m, l[c]); }
    float s = 0.f;
    #pragma unroll
    for (int c = 0; c < C1; c++) { l[c] = expf(l[c] - m); s += l[c]; }
    float inv = -1.0f / s;
    float* dst = g_probT + (size_t)b * C1 * QP + q;
    #pragma unroll
    for (int c = 0; c < C1; c++) dst[(size_t)c * QP] = l[c] * inv;
    g_lse[b * QQ + q] = m + logf(s);
}

// ---------------------------------------------------------------------------
// Kernel 1: cost matrix. grid (8, B) x 256; block covers 16 targets, thread
// owns 4 adjacent queries. Packed f32x2 diffs, scalar sum with free |src|
// FADD modifiers, LDG.128 class costs, STG.128 out.
// ---------------------------------------------------------------------------
__global__ void __launch_bounds__(256) cost_kernel(
    const float* __restrict__ pb, const int* __restrict__ tl,
    const float* __restrict__ tb)
{
    int b   = blockIdx.y;
    int t0  = blockIdx.x * 16;
    int tid = threadIdx.x;

    __shared__ ulonglong2 sA[16];        // ((-tx,-tx),(-ty,-ty))
    __shared__ ulonglong2 sB[16];        // ((-tw,-tw),(-th,-th))
    __shared__ const float* sPtr[16];    // probT row for label[t]

    if (tid < 16) {
        int t = t0 + tid;
        const float4 tb4 = ((const float4*)tb)[b * TT + t];
        sA[tid].x = pk2(-tb4.x, -tb4.x);
        sA[tid].y = pk2(-tb4.y, -tb4.y);
        sB[tid].x = pk2(-tb4.z, -tb4.z);
        sB[tid].y = pk2(-tb4.w, -tb4.w);
        sPtr[tid] = g_probT + ((size_t)b * C1 + tl[b * TT + t]) * QP;
    }
    __syncthreads();
    if (tid >= 225) return;             // 225 quads cover q = 0..899

    int q0 = tid * 4;
    const float4 p0 = ((const float4*)pb)[b * QQ + q0];
    const float4 p1 = ((const float4*)pb)[b * QQ + q0 + 1];
    const float4 p2 = ((const float4*)pb)[b * QQ + q0 + 2];
    const float4 p3 = ((const float4*)pb)[b * QQ + q0 + 3];
    u64 px0 = pk2(p0.x, p1.x), px1 = pk2(p2.x, p3.x);
    u64 py0 = pk2(p0.y, p1.y), py1 = pk2(p2.y, p3.y);
    u64 pw0 = pk2(p0.z, p1.z), pw1 = pk2(p2.z, p3.z);
    u64 ph0 = pk2(p0.w, p1.w), ph1 = pk2(p2.w, p3.w);

    float4* out = (float4*)(g_cost + (size_t)b * TT * QQ + (size_t)t0 * QQ + q0);

    #pragma unroll 4
    for (int tt = 0; tt < 16; tt++) {
        ulonglong2 A = sA[tt];
        ulonglong2 Bv = sB[tt];
        const float4 cc = *(const float4*)(sPtr[tt] + q0);

        u64 dx0 = addx2(px0, A.x),  dx1 = addx2(px1, A.x);
        u64 dy0 = addx2(py0, A.y),  dy1 = addx2(py1, A.y);
        u64 dw0 = addx2(pw0, Bv.x), dw1 = addx2(pw1, Bv.x);
        u64 dh0 = addx2(ph0, Bv.y), dh1 = addx2(ph1, Bv.y);

        float xl, xh, yl, yh, wl, wh, hl, hh;
        float4 r;
        up2(dx0, xl, xh); up2(dy0, yl, yh); up2(dw0, wl, wh); up2(dh0, hl, hh);
        r.x = (fabsf(xl) + fabsf(yl)) + (fabsf(wl) + fabsf(hl)) + cc.x;
        r.y = (fabsf(xh) + fabsf(yh)) + (fabsf(wh) + fabsf(hh)) + cc.y;
        up2(dx1, xl, xh); up2(dy1, yl, yh); up2(dw1, wl, wh); up2(dh1, hl, hh);
        r.z = (fabsf(xl) + fabsf(yl)) + (fabsf(wl) + fabsf(hl)) + cc.z;
        r.w = (fabsf(xh) + fabsf(yh)) + (fabsf(wh) + fabsf(hh)) + cc.w;

        *out = r;
        out += QQ / 4;
    }
}

// ---------------------------------------------------------------------------
// Kernel 2: exact rectangular assignment, successive shortest paths with JV
// row-reduction init. FP32 duals. One block per batch.
// ---------------------------------------------------------------------------
__global__ void __launch_bounds__(256) hungarian_kernel()
{
    int b = blockIdx.x;
    const float* cost = g_cost + (size_t)b * TT * QQ;

    __shared__ float v[QQ + 1];
    __shared__ float spc[QQ + 1];
    __shared__ float u[TT + 1];
    __shared__ short p[QQ + 1];
    __shared__ short way[QQ + 1];
    __shared__ unsigned char used[QQ + 1];
    __shared__ int   claim[QQ + 1];
    __shared__ short tree[QQ + 1];
    __shared__ short rowargmin[TT];
    __shared__ short freerows[TT];
    __shared__ int   s_nfree;
    __shared__ int   s_ntree;
    __shared__ float s_minval;
    __shared__ float s_ui0;
    __shared__ int   s_j1;
    __shared__ int   s_i0;
    __shared__ int   s_done;
    __shared__ float red_v[8];
    __shared__ int   red_j[8];

    int tid = threadIdx.x;
    int lane = tid & 31, wid = tid >> 5;

    for (int j = tid; j <= QQ; j += 256) { v[j] = 0.0f; p[j] = 0; claim[j] = 0x7fffffff; }
    if (tid == 0) s_nfree = 0;
    __syncthreads();

    // ---- phase 1: row minima (+argmin, first-index tie-break) ----
    for (int t = wid; t < TT; t += 8) {
        const float* crow = cost + (size_t)t * QQ;
        float bv = FLT_MAX;
        int   bj = 0x7fffffff;
        for (int j = lane; j < QQ; j += 32) {
            float c = crow[j];
            if (c < bv) { bv = c; bj = j; }
        }
        #pragma unroll
        for (int o = 16; o; o >>= 1) {
            float ov = __shfl_down_sync(0xffffffffu, bv, o);
            int   oj = __shfl_down_sync(0xffffffffu, bj, o);
            if (ov < bv || (ov == bv && oj < bj)) { bv = ov; bj = oj; }
        }
        if (lane == 0) {
            u[t + 1] = bv;
            rowargmin[t] = (short)bj;
        }
    }
    __syncthreads();

    // ---- phase 2: greedy matching (winner = lowest row index) ----
    if (tid < TT) atomicMin(&claim[rowargmin[tid] + 1], tid);
    __syncthreads();
    if (tid < TT) {
        int j = rowargmin[tid] + 1;
        if (claim[j] == tid) p[j] = (short)(tid + 1);
        else {
            int k = atomicAdd(&s_nfree, 1);
            freerows[k] = (short)(tid + 1);
        }
    }
    __syncthreads();
    int nfree = s_nfree;

    // ---- phase 3: Dijkstra augment for each free row ----
    for (int fi = 0; fi < nfree; fi++) {
        int i = freerows[fi];
        for (int j = tid; j <= QQ; j += 256) { spc[j] = FLT_MAX; used[j] = 0; }
        if (tid == 0) {
            p[0] = (short)i;
            spc[0] = 0.0f;
            s_minval = 0.0f;
            s_ui0 = u[i];
            s_i0 = i;
            s_j1 = 0;
            s_done = 0;
            used[0] = 1;
            tree[0] = 0;
            s_ntree = 1;
        }
        __syncthreads();

        while (1) {
            int   j1prev = s_j1;
            float minVal = s_minval;
            float ui0    = s_ui0;
            int   i0     = s_i0;
            const float* crow = cost + (size_t)(i0 - 1) * QQ;

            float bv = FLT_MAX;
            int   bj = 0x7fffffff;
            float base = minVal - ui0;
            for (int j = tid + 1; j <= QQ; j += 256) {
                if (!used[j] && j != j1prev) {
                    float r = base + crow[j - 1] - v[j];
                    float m = spc[j];
                    if (r < m) { m = r; spc[j] = r; way[j] = (short)j1prev; }
                    if (m < bv) { bv = m; bj = j; }
                }
            }
            #pragma unroll
            for (int o = 16; o; o >>= 1) {
                float ov = __shfl_down_sync(0xffffffffu, bv, o);
                int   oj = __shfl_down_sync(0xffffffffu, bj, o);
                if (ov < bv || (ov == bv && oj < bj)) { bv = ov; bj = oj; }
            }
            if (lane == 0) { red_v[wid] = bv; red_j[wid] = bj; }
            __syncthreads();
            if (wid == 0) {
                bv = (lane < 8) ? red_v[lane] : FLT_MAX;
                bj = (lane < 8) ? red_j[lane] : 0x7fffffff;
                #pragma unroll
                for (int o = 4; o; o >>= 1) {
                    float ov = __shfl_down_sync(0xffffffffu, bv, o);
                    int   oj = __shfl_down_sync(0xffffffffu, bj, o);
                    if (ov < bv || (ov == bv && oj < bj)) { bv = ov; bj = oj; }
                }
                if (lane == 0) {
                    if (j1prev != 0) {
                        used[j1prev] = 1;
                        tree[s_ntree++] = (short)j1prev;
                    }
                    int r = p[bj];
                    s_minval = bv;
                    s_j1 = bj;
                    if (r == 0) s_done = 1;
                    else { s_i0 = r; s_ui0 = u[r]; }
                }
            }
            __syncthreads();
            if (s_done) break;
        }

        float minF = s_minval;
        int sink = s_j1;
        int ntree = s_ntree;

        for (int k = tid; k < ntree; k += 256) {
            int j = tree[k];
            float d = minF - spc[j];
            u[p[j]] += d;
            v[j]    -= d;
        }
        __syncthreads();

        if (tid == 0) {
            int j0 = sink;
            while (j0) {
                int jn = way[j0];
                p[j0] = p[jn];
                j0 = jn;
            }
        }
        __syncthreads();
    }

    for (int j = tid + 1; j <= QQ; j += 256) {
        int r = p[j];
        if (r > 0) g_pred[b * TT + (r - 1)] = j - 1;
    }
}

// ---------------------------------------------------------------------------
// Kernel 3: per-batch losses + fused deterministic finalize (last block).
// ---------------------------------------------------------------------------
__global__ void __launch_bounds__(256) loss_kernel(
    const float* __restrict__ pc, const float* __restrict__ pb,
    const int* __restrict__ tl, const float* __restrict__ tb,
    float* __restrict__ outp)
{
    int b = blockIdx.x, tid = threadIdx.x;
    int lane = tid & 31, wid = tid >> 5;

    __shared__ short tc[QQ];
    __shared__ double red[8][4];
    __shared__ int s_last;

    for (int q = tid; q < QQ; q += 256) tc[q] = 13;
    __syncthreads();

    double l1sum = 0.0, gsum = 0.0;
    if (tid < TT) {
        int t = tid;
        int q = g_pred[b * TT + t];
        int lab = tl[b * TT + t];
        tc[q] = (short)lab;

        const float* pbx = pb + ((size_t)b * QQ + q) * 4;
        const float* tbx = tb + ((size_t)b * TT + t) * 4;
        float px = pbx[0], py = pbx[1], pw = pbx[2], ph = pbx[3];
        float tx = tbx[0], ty = tbx[1], tw = tbx[2], th = tbx[3];

        l1sum = (double)(fabsf(px - tx) + fabsf(py - ty) +
                         fabsf(pw - tw) + fabsf(ph - th));

        float p1x = px - 0.5f * pw, p1y = py - 0.5f * ph;
        float p2x = px + 0.5f * pw, p2y = py + 0.5f * ph;
        float t1x = tx - 0.5f * tw, t1y = ty - 0.5f * th;
        float t2x = tx + 0.5f * tw, t2y = ty + 0.5f * th;
        float a1 = (p2x - p1x) * (p2y - p1y);
        float a2 = (t2x - t1x) * (t2y - t1y);
        float ltx = fmaxf(p1x, t1x), lty = fmaxf(p1y, t1y);
        float rbx = fminf(p2x, t2x), rby = fminf(p2y, t2y);
        float iw = fmaxf(rbx - ltx, 0.f), ih = fmaxf(rby - lty, 0.f);
        float inter = iw * ih;
        float uni = a1 + a2 - inter;
        float iou = inter / uni;
        float cx1 = fminf(p1x, t1x), cy1 = fminf(p1y, t1y);
        float cx2 = fmaxf(p2x, t2x), cy2 = fmaxf(p2y, t2y);
        float ac = (cx2 - cx1) * (cy2 - cy1);
        gsum = (double)(iou - (ac - uni) / ac);
    }
    __syncthreads();

    double clsum = 0.0, wsum = 0.0;
    for (int q = tid; q < QQ; q += 256) {
        int c = tc[q];
        float w = (c == 13) ? 0.05f : 1.0f;
        float nll = g_lse[b * QQ + q] - pc[((size_t)b * QQ + q) * C1 + c];
        clsum += (double)(w * nll);
        wsum  += (double)w;
    }

    #pragma unroll
    for (int o = 16; o; o >>= 1) {
        l1sum += __shfl_down_sync(0xffffffffu, l1sum, o);
        gsum  += __shfl_down_sync(0xffffffffu, gsum, o);
        clsum += __shfl_down_sync(0xffffffffu, clsum, o);
        wsum  += __shfl_down_sync(0xffffffffu, wsum, o);
    }
    if (lane == 0) { red[wid][0] = l1sum; red[wid][1] = gsum; red[wid][2] = clsum; red[wid][3] = wsum; }
    __syncthreads();
    if (tid == 0) {
        double a = 0, g = 0, c = 0, w = 0;
        #pragma unroll
        for (int k = 0; k < 8; k++) { a += red[k][0]; g += red[k][1]; c += red[k][2]; w += red[k][3]; }
        double l1mean = a / (double)(TT * 4);
        double bbox = 5.0 * l1mean + 2.0 * (1.0 - g / (double)TT);
        double cls = c / w;
        g_partial[b] = (float)(bbox + cls);
        __threadfence();
        unsigned old = atomicAdd(&g_count, 1u);
        s_last = (old == BB - 1) ? 1 : 0;
    }
    __syncthreads();

    if (s_last) {
        __threadfence();   // acquire: make all g_partial visible
        __shared__ double sw[2];
        double s = (tid < BB) ? (double)g_partial[tid] : 0.0;
        #pragma unroll
        for (int o = 16; o; o >>= 1) s += __shfl_down_sync(0xffffffffu, s, o);
        if (tid < 64 && lane == 0) sw[wid] = s;
        __syncthreads();
        if (tid == 0) {
            outp[0] = (float)((sw[0] + sw[1]) / (double)(BB * TT));
            g_count = 0;   // reset for next graph replay
        }
    }
}

// ---------------------------------------------------------------------------
extern "C" void kernel_launch(void* const* d_in, const int* in_sizes, int n_in,
                              void* d_out, int out_size)
{
    const float* pc = (const float*)d_in[0];  // predicted_class [B,Q,14]
    const float* pb = (const float*)d_in[1];  // predicted_bbox  [B,Q,4]
    const int*   tl = (const int*)d_in[2];    // target_labels   [B,T]
    const float* tb = (const float*)d_in[3];  // target_boxes    [B,T,4]

    softmax_kernel<<<dim3(4, BB), 256>>>(pc);
    cost_kernel<<<dim3(8, BB), 256>>>(pb, tl, tb);
    hungarian_kernel<<<BB, 256>>>();
    loss_kernel<<<BB, 256>>>(pc, pb, tl, tb, (float*)d_out);
}